// round 16
// baseline (speedup 1.0000x reference)
#include <cuda_runtime.h>
#include <cuda_fp16.h>
#include <float.h>
#include <stdint.h>

// Problem constants
constexpr int Bn = 8;
constexpr int Ln = 2048;
constexpr int Hn = 1024;

constexpr int NT = 256;  // 8 warps, 2x4 warp grid

// Scratch (static device arrays; allocation-free per harness rules)
__device__ __half g_hx[(size_t)Bn * Ln * Hn];   // 32 MB fp16 input
__device__ __half g_hwq[(size_t)Hn * Hn];
__device__ __half g_hwk[(size_t)Hn * Hn];
__device__ __half g_hwv[(size_t)Hn * Hn];
__device__ __half g_q[(size_t)Bn * Ln * Hn];    // pre-scaled by 1/H
__device__ __half g_k[(size_t)Bn * Ln * Hn];
__device__ __half g_vT[(size_t)Bn * Hn * Ln];   // [b][h][l]
__device__ __half g_e[(size_t)Bn * Ln * Ln];    // 64 MB unnormalized exp(S)
__device__ float  g_zp[(size_t)Bn * Ln * 64];   // per-(row, slab) partial sums
__device__ float  g_z[(size_t)Bn * Ln];         // per-row 1/sum

// ---------------------------------------------------------------------------
// PTX helpers (Ampere-class only: compile clean at target sm_103)
// ---------------------------------------------------------------------------
__device__ __forceinline__ uint32_t smem_u32(const void* p) {
    uint32_t a;
    asm("{ .reg .u64 t; cvta.to.shared.u64 t, %1; cvt.u32.u64 %0, t; }"
        : "=r"(a) : "l"(p));
    return a;
}
__device__ __forceinline__ void cp16(uint32_t dst, const void* src) {
    asm volatile("cp.async.cg.shared.global [%0], [%1], 16;"
                 :: "r"(dst), "l"(src));
}
__device__ __forceinline__ void cp_commit() {
    asm volatile("cp.async.commit_group;" ::: "memory");
}
template <int N>
__device__ __forceinline__ void cp_wait() {
    asm volatile("cp.async.wait_group %0;" :: "n"(N) : "memory");
}
__device__ __forceinline__ void ldsm4(uint32_t& r0, uint32_t& r1, uint32_t& r2,
                                      uint32_t& r3, uint32_t a) {
    asm volatile("ldmatrix.sync.aligned.m8n8.x4.shared.b16 {%0,%1,%2,%3}, [%4];"
                 : "=r"(r0), "=r"(r1), "=r"(r2), "=r"(r3) : "r"(a));
}
__device__ __forceinline__ void mma_f16(float c[4], const uint32_t a[4],
                                        const uint32_t b[2]) {
    asm volatile(
        "mma.sync.aligned.m16n8k16.row.col.f32.f16.f16.f32 "
        "{%0,%1,%2,%3}, {%4,%5,%6,%7}, {%8,%9}, {%0,%1,%2,%3};"
        : "+f"(c[0]), "+f"(c[1]), "+f"(c[2]), "+f"(c[3])
        : "r"(a[0]), "r"(a[1]), "r"(a[2]), "r"(a[3]), "r"(b[0]), "r"(b[1]));
}
__device__ __forceinline__ uint32_t swz(uint32_t b) { return b ^ ((b >> 3) & 0x70); }

// ---------------------------------------------------------------------------
// Core (MF*32)x128xK NT GEMM, templated on A-tile rows (MF m-frags per warp).
// A [M,K], B [N,K] fp16 row-major, fp32 accumulate. 3-stage cp.async,
// ldmatrix fragments, one barrier per k-tile. Swizzle computed inline per
// access (proven fastest; do NOT hoist via XOR — measured 44% regression).
// MF=4: 128x128 CTA tile (64x32 warp tile). MF=2: 64x128 (32x32 warp tile).
// ---------------------------------------------------------------------------
template <int MF>
__device__ __forceinline__ void gemm_nt(const __half* __restrict__ A,
                                        const __half* __restrict__ B,
                                        int lda, int ldb, int K,
                                        uint32_t sbase, float acc[MF][4][4]) {
    constexpr int A_BYTES = MF * 32 * 128;          // A rows x 128B
    constexpr int STG = A_BYTES + 16 * 1024;        // + B 128x128B

    const int tid = threadIdx.x;
    const int lane = tid & 31, wid = tid >> 5;
    const int wm = (wid >> 2) * (MF * 16), wn = (wid & 3) * 32;

    auto stage_load = [&](int k0, int s) {
        uint32_t slot = sbase + s * STG;
#pragma unroll
        for (int it = 0; it < MF; it++) {
            int f = tid + it * NT;
            int row = f >> 3, cb = (f & 7) << 4;
            cp16(slot + swz(row * 128 + cb),
                 (const char*)(A + (size_t)row * lda + k0) + cb);
        }
#pragma unroll
        for (int it = 0; it < 4; it++) {
            int f = tid + it * NT;
            int row = f >> 3, cb = (f & 7) << 4;
            cp16(slot + A_BYTES + swz(row * 128 + cb),
                 (const char*)(B + (size_t)row * ldb + k0) + cb);
        }
        cp_commit();
    };

    // ldmatrix lane addressing (canonical m16n8k16 fragment layout)
    const int rA = ((lane >> 3) & 1) * 8 + (lane & 7);
    const int sA = (lane >> 4) * 16;
    const int rB = ((lane >> 4) & 1) * 8 + (lane & 7);
    const int sB = ((lane >> 3) & 1) * 16;

    const int niter = K / 64;
    stage_load(0, 0);
    stage_load(64, 1);

    for (int i = 0; i < niter; i++) {
        cp_wait<1>();
        __syncthreads();   // data(i) visible; all warps done with stage (i-1)%3
        if (i + 2 < niter) stage_load((i + 2) * 64, (i + 2) % 3);
        else cp_commit();                  // keep group count aligned

        uint32_t slot = sbase + (i % 3) * STG;
#pragma unroll
        for (int kk = 0; kk < 4; kk++) {
            uint32_t a[MF][4], b[4][2];
#pragma unroll
            for (int im = 0; im < MF; im++) {
                int row = wm + im * 16 + rA;
                ldsm4(a[im][0], a[im][1], a[im][2], a[im][3],
                      slot + swz(row * 128 + kk * 32 + sA));
            }
#pragma unroll
            for (int p = 0; p < 2; p++) {
                int row = wn + p * 16 + rB;
                ldsm4(b[2 * p][0], b[2 * p][1], b[2 * p + 1][0], b[2 * p + 1][1],
                      slot + A_BYTES + swz(row * 128 + kk * 32 + sB));
            }
#pragma unroll
            for (int im = 0; im < MF; im++)
#pragma unroll
                for (int jn = 0; jn < 4; jn++)
                    mma_f16(acc[im][jn], a[im], b[jn]);
        }
    }
    __syncthreads();       // protect smem before epilogue / exit
}

constexpr size_t SMEM_BIG = 1024 + 3 * (16 * 1024 + 16 * 1024);  // MF=4
constexpr size_t SMEM_SML = 1024 + 3 * (8 * 1024 + 16 * 1024);   // MF=2

#define GEMM_SMEM_SETUP()                                                      \
    extern __shared__ char smem_raw[];                                         \
    char* sb = (char*)(((uintptr_t)smem_raw + 1023) & ~(uintptr_t)1023);       \
    uint32_t sbase = smem_u32(sb);                                             \
    const int lane = threadIdx.x & 31;                                         \
    const int wid = threadIdx.x >> 5;

// ---------------------------------------------------------------------------
// Kernel 0: all fp32 -> fp16 converts in ONE launch (y: 0=x, 1..3=weights)
// ---------------------------------------------------------------------------
__global__ __launch_bounds__(256) void cvt_all_kernel(
    const float* __restrict__ x, const float* __restrict__ wq,
    const float* __restrict__ wk, const float* __restrict__ wv) {
    const int which = blockIdx.y;
    const float* src;
    __half* dst;
    int n4;
    if (which == 0) {
        src = x;
        dst = g_hx;
        n4 = Bn * Ln * Hn / 4;
    } else {
        src = (which == 1) ? wq : (which == 2) ? wk : wv;
        dst = (which == 1) ? g_hwq : (which == 2) ? g_hwk : g_hwv;
        n4 = Hn * Hn / 4;
    }
    for (int i = blockIdx.x * blockDim.x + threadIdx.x; i < n4;
         i += gridDim.x * blockDim.x) {
        float4 v = ((const float4*)src)[i];
        __half2 h0 = __floats2half2_rn(v.x, v.y);
        __half2 h1 = __floats2half2_rn(v.z, v.w);
        uint2 u;
        u.x = *(uint32_t*)&h0;
        u.y = *(uint32_t*)&h1;
        ((uint2*)dst)[i] = u;
    }
}

// ---------------------------------------------------------------------------
// Kernel 1: QKV projections (fp16 in/out). z selects q/k/v.
// q pre-scaled by 1/H. v written TRANSPOSED [b][h][l].
// ---------------------------------------------------------------------------
__global__ __launch_bounds__(NT, 2) void qkv_kernel(
    const float* __restrict__ bq, const float* __restrict__ bk,
    const float* __restrict__ bv) {
    const int z = blockIdx.z;
    const __half* W = (z == 0) ? g_hwq : (z == 1) ? g_hwk : g_hwv;
    const float* bias = (z == 0) ? bq : (z == 1) ? bk : bv;
    const float scale = (z == 0) ? (1.0f / (float)Hn) : 1.0f;

    GEMM_SMEM_SETUP();

    const __half* A = g_hx + (size_t)blockIdx.y * 128 * Hn;
    const __half* Bm = W + (size_t)blockIdx.x * 128 * Hn;
    float acc[4][4][4] = {};
    gemm_nt<4>(A, Bm, Hn, Hn, Hn, sbase, acc);

    const int row0 = blockIdx.y * 128 + (wid >> 2) * 64 + (lane >> 2);
    const int col0 = blockIdx.x * 128 + (wid & 3) * 32 + (lane & 3) * 2;

    if (z < 2) {
        __half* out = (z == 0) ? g_q : g_k;
#pragma unroll
        for (int im = 0; im < 4; im++) {
#pragma unroll
            for (int jn = 0; jn < 4; jn++) {
                int r = row0 + im * 16;
                int c = col0 + jn * 8;
                float2 b2 = *(const float2*)&bias[c];
                __half2 h0 = __floats2half2_rn((acc[im][jn][0] + b2.x) * scale,
                                               (acc[im][jn][1] + b2.y) * scale);
                __half2 h1 = __floats2half2_rn((acc[im][jn][2] + b2.x) * scale,
                                               (acc[im][jn][3] + b2.y) * scale);
                *(__half2*)&out[(size_t)r * Hn + c] = h0;
                *(__half2*)&out[(size_t)(r + 8) * Hn + c] = h1;
            }
        }
    } else {
#pragma unroll
        for (int im = 0; im < 4; im++) {
            int r = row0 + im * 16;
            int b = r >> 11;               // r / Ln
            int l = r & (Ln - 1);
            size_t vb = (size_t)b * Hn * Ln;
#pragma unroll
            for (int jn = 0; jn < 4; jn++) {
                int c = col0 + jn * 8;
                float2 b2 = *(const float2*)&bias[c];
                g_vT[vb + (size_t)c * Ln + l]           = __float2half_rn(acc[im][jn][0] + b2.x);
                g_vT[vb + (size_t)(c + 1) * Ln + l]     = __float2half_rn(acc[im][jn][1] + b2.y);
                g_vT[vb + (size_t)c * Ln + l + 8]       = __float2half_rn(acc[im][jn][2] + b2.x);
                g_vT[vb + (size_t)(c + 1) * Ln + l + 8] = __float2half_rn(acc[im][jn][3] + b2.y);
            }
        }
    }
}

// ---------------------------------------------------------------------------
// Kernel 2: E = exp(q @ k^T), diagonal -> 0, fp16 out + DETERMINISTIC
// per-(row, 32-col-slab) partial sums into g_zp (distinct address per writer;
// no atomics). |s| < 0.1 so exp needs no max subtraction.
// ---------------------------------------------------------------------------
__global__ __launch_bounds__(NT, 2) void score_kernel() {
    const int bz = blockIdx.z;

    GEMM_SMEM_SETUP();

    const __half* A = g_q + (size_t)bz * Ln * Hn + (size_t)blockIdx.y * 128 * Hn;
    const __half* Bm = g_k + (size_t)bz * Ln * Hn + (size_t)blockIdx.x * 128 * Hn;
    float acc[4][4][4] = {};
    gemm_nt<4>(A, Bm, Hn, Hn, Hn, sbase, acc);

    __half* out = g_e + (size_t)bz * Ln * Ln;
    const int row0 = blockIdx.y * 128 + (wid >> 2) * 64 + (lane >> 2);
    const int col0 = blockIdx.x * 128 + (wid & 3) * 32 + (lane & 3) * 2;
    const int slab = blockIdx.x * 4 + (wid & 3);   // 64 slabs of 32 cols

#pragma unroll
    for (int im = 0; im < 4; im++) {
        int r = row0 + im * 16;
        float sr = 0.0f, sr8 = 0.0f;
#pragma unroll
        for (int jn = 0; jn < 4; jn++) {
            int c = col0 + jn * 8;
            float v0 = (r == c)         ? 0.0f : __expf(acc[im][jn][0]);
            float v1 = (r == c + 1)     ? 0.0f : __expf(acc[im][jn][1]);
            float v2 = (r + 8 == c)     ? 0.0f : __expf(acc[im][jn][2]);
            float v3 = (r + 8 == c + 1) ? 0.0f : __expf(acc[im][jn][3]);
            sr += v0 + v1;
            sr8 += v2 + v3;
            *(__half2*)&out[(size_t)r * Ln + c] = __floats2half2_rn(v0, v1);
            *(__half2*)&out[(size_t)(r + 8) * Ln + c] = __floats2half2_rn(v2, v3);
        }
        // Reduce over the 4 column-lanes (lane bits [0:1]) of this row
        sr  += __shfl_xor_sync(0xffffffff, sr, 1);
        sr  += __shfl_xor_sync(0xffffffff, sr, 2);
        sr8 += __shfl_xor_sync(0xffffffff, sr8, 1);
        sr8 += __shfl_xor_sync(0xffffffff, sr8, 2);
        if ((lane & 3) == 0) {
            g_zp[((size_t)bz * Ln + r) * 64 + slab] = sr;
            g_zp[((size_t)bz * Ln + r + 8) * 64 + slab] = sr8;
        }
    }
}

// ---------------------------------------------------------------------------
// Kernel 3: invz — reduce 64 partials per row -> g_z = 1/sum.
// One warp per row; fully coalesced.
// ---------------------------------------------------------------------------
__global__ __launch_bounds__(256) void invz_kernel() {
    const int row = blockIdx.x * 8 + (threadIdx.x >> 5);
    const int lane = threadIdx.x & 31;
    const float* p = g_zp + (size_t)row * 64;
    float s = p[lane] + p[lane + 32];
#pragma unroll
    for (int m = 16; m > 0; m >>= 1) s += __shfl_xor_sync(0xffffffff, s, m);
    if (lane == 0) g_z[row] = 1.0f / s;
}

// ---------------------------------------------------------------------------
// Kernel 4: O = diag(invZ) * (E @ vT), fp32 out. 64-row CTA tiles (MF=2) to
// double the CTA count and kill the partial-wave tail.
// ---------------------------------------------------------------------------
__global__ __launch_bounds__(NT, 2) void pv_kernel(float* __restrict__ out) {
    const int bz = blockIdx.z;

    GEMM_SMEM_SETUP();

    const __half* A = g_e + (size_t)bz * Ln * Ln + (size_t)blockIdx.y * 64 * Ln;
    const __half* Bm = g_vT + (size_t)bz * Hn * Ln + (size_t)blockIdx.x * 128 * Ln;
    float acc[2][4][4] = {};
    gemm_nt<2>(A, Bm, Ln, Ln, Ln, sbase, acc);

    float* o = out + (size_t)bz * Ln * Hn;
    const int row0 = blockIdx.y * 64 + (wid >> 2) * 32 + (lane >> 2);
    const int col0 = blockIdx.x * 128 + (wid & 3) * 32 + (lane & 3) * 2;

#pragma unroll
    for (int im = 0; im < 2; im++) {
        int r = row0 + im * 16;
        float z0 = g_z[(size_t)bz * Ln + r];
        float z1 = g_z[(size_t)bz * Ln + r + 8];
#pragma unroll
        for (int jn = 0; jn < 4; jn++) {
            int c = col0 + jn * 8;
            *(float2*)&o[(size_t)r * Hn + c] =
                make_float2(acc[im][jn][0] * z0, acc[im][jn][1] * z0);
            *(float2*)&o[(size_t)(r + 8) * Hn + c] =
                make_float2(acc[im][jn][2] * z1, acc[im][jn][3] * z1);
        }
    }
}

// ---------------------------------------------------------------------------
extern "C" void kernel_launch(void* const* d_in, const int* in_sizes, int n_in,
                              void* d_out, int out_size) {
    const float* x  = (const float*)d_in[0];
    const float* Wq = (const float*)d_in[1];
    const float* bq = (const float*)d_in[2];
    const float* Wk = (const float*)d_in[3];
    const float* bk = (const float*)d_in[4];
    const float* Wv = (const float*)d_in[5];
    const float* bv = (const float*)d_in[6];
    float* out = (float*)d_out;

    cudaFuncSetAttribute(qkv_kernel, cudaFuncAttributeMaxDynamicSharedMemorySize, (int)SMEM_BIG);
    cudaFuncSetAttribute(score_kernel, cudaFuncAttributeMaxDynamicSharedMemorySize, (int)SMEM_BIG);
    cudaFuncSetAttribute(pv_kernel, cudaFuncAttributeMaxDynamicSharedMemorySize, (int)SMEM_SML);

    // All converts in one launch: y=0 covers x with grid-stride; y=1..3 weights.
    cvt_all_kernel<<<dim3(4096, 4), 256>>>(x, Wq, Wk, Wv);

    dim3 blk(NT);
    // QKV: M = 16384 (128 tiles), N = 1024 (8 tiles), z in {q,k,v}
    qkv_kernel<<<dim3(8, 128, 3), blk, SMEM_BIG>>>(bq, bk, bv);
    // Scores+exp+partial rowsums: per batch 2048x2048 -> (16, 16, 8)
    score_kernel<<<dim3(16, 16, Bn), blk, SMEM_BIG>>>();
    // Reduce partials -> 1/Z (one warp per row)
    invz_kernel<<<Bn * Ln / 8, 256>>>();
    // Output (normalized in epilogue): 64-row tiles -> (8, 32, 8) = 2048 CTAs
    pv_kernel<<<dim3(8, 32, Bn), blk, SMEM_SML>>>(out);
}

// round 17
// speedup vs baseline: 1.0269x; 1.0269x over previous
#include <cuda_runtime.h>
#include <cuda_fp16.h>
#include <float.h>
#include <stdint.h>

// Problem constants
constexpr int Bn = 8;
constexpr int Ln = 2048;
constexpr int Hn = 1024;

constexpr int NT = 256;                // 8 warps, 2x4 grid of 64x32 warp tiles
constexpr int STAGE_BYTES = 32 * 1024; // A 16KB + B 16KB
constexpr int B_OFF = 16 * 1024;
constexpr size_t SMEM_BYTES = 1024 + 3 * STAGE_BYTES;

// Scratch (static device arrays; allocation-free per harness rules)
__device__ __half g_hx[(size_t)Bn * Ln * Hn];   // 32 MB fp16 input
__device__ __half g_hwq[(size_t)Hn * Hn];
__device__ __half g_hwk[(size_t)Hn * Hn];
__device__ __half g_hwv[(size_t)Hn * Hn];
__device__ __half g_q[(size_t)Bn * Ln * Hn];    // pre-scaled by 1/H
__device__ __half g_k[(size_t)Bn * Ln * Hn];
__device__ __half g_vT[(size_t)Bn * Hn * Ln];   // [b][h][l]
__device__ __half g_e[(size_t)Bn * Ln * Ln];    // 64 MB unnormalized exp(S)
__device__ float  g_zp[(size_t)Bn * Ln * 64];   // per-(row, slab) partial sums
__device__ float  g_z[(size_t)Bn * Ln];         // per-row 1/sum

// ---------------------------------------------------------------------------
// PTX helpers (Ampere-class only: compile clean at target sm_103)
// ---------------------------------------------------------------------------
__device__ __forceinline__ uint32_t smem_u32(const void* p) {
    uint32_t a;
    asm("{ .reg .u64 t; cvta.to.shared.u64 t, %1; cvt.u32.u64 %0, t; }"
        : "=r"(a) : "l"(p));
    return a;
}
__device__ __forceinline__ void cp16(uint32_t dst, const void* src) {
    asm volatile("cp.async.cg.shared.global [%0], [%1], 16;"
                 :: "r"(dst), "l"(src));
}
__device__ __forceinline__ void cp_commit() {
    asm volatile("cp.async.commit_group;" ::: "memory");
}
template <int N>
__device__ __forceinline__ void cp_wait() {
    asm volatile("cp.async.wait_group %0;" :: "n"(N) : "memory");
}
__device__ __forceinline__ void ldsm4(uint32_t& r0, uint32_t& r1, uint32_t& r2,
                                      uint32_t& r3, uint32_t a) {
    asm volatile("ldmatrix.sync.aligned.m8n8.x4.shared.b16 {%0,%1,%2,%3}, [%4];"
                 : "=r"(r0), "=r"(r1), "=r"(r2), "=r"(r3) : "r"(a));
}
__device__ __forceinline__ void mma_f16(float c[4], const uint32_t a[4],
                                        const uint32_t b[2]) {
    asm volatile(
        "mma.sync.aligned.m16n8k16.row.col.f32.f16.f16.f32 "
        "{%0,%1,%2,%3}, {%4,%5,%6,%7}, {%8,%9}, {%0,%1,%2,%3};"
        : "+f"(c[0]), "+f"(c[1]), "+f"(c[2]), "+f"(c[3])
        : "r"(a[0]), "r"(a[1]), "r"(a[2]), "r"(a[3]), "r"(b[0]), "r"(b[1]));
}
__device__ __forceinline__ uint32_t swz(uint32_t b) { return b ^ ((b >> 3) & 0x70); }

// ---------------------------------------------------------------------------
// Core 128x128xK NT GEMM: A [M,K], B [N,K] fp16 row-major, fp32 accumulate.
// 3-stage cp.async pipeline, ldmatrix fragment loads, one barrier per k-tile.
// EXACT champion configuration: swizzle computed inline per access (do NOT
// hoist via XOR tricks — measured 44% regression); 128-row M tiles (do NOT
// shrink to 64 — halving M doubles B traffic per FLOP, measured +27us on pv).
// ---------------------------------------------------------------------------
__device__ __forceinline__ void gemm_nt(const __half* __restrict__ A,
                                        const __half* __restrict__ B,
                                        int lda, int ldb, int K,
                                        uint32_t sbase, float acc[4][4][4]) {
    const int tid = threadIdx.x;
    const int lane = tid & 31, wid = tid >> 5;
    const int wm = (wid >> 2) * 64, wn = (wid & 3) * 32;

    auto stage_load = [&](int k0, int s) {
        uint32_t slot = sbase + s * STAGE_BYTES;
#pragma unroll
        for (int it = 0; it < 4; it++) {
            int f = tid + it * NT;
            int row = f >> 3, cb = (f & 7) << 4;
            cp16(slot + swz(row * 128 + cb),
                 (const char*)(A + (size_t)row * lda + k0) + cb);
        }
#pragma unroll
        for (int it = 0; it < 4; it++) {
            int f = tid + it * NT;
            int row = f >> 3, cb = (f & 7) << 4;
            cp16(slot + B_OFF + swz(row * 128 + cb),
                 (const char*)(B + (size_t)row * ldb + k0) + cb);
        }
        cp_commit();
    };

    // ldmatrix lane addressing (canonical m16n8k16 fragment layout)
    const int rA = ((lane >> 3) & 1) * 8 + (lane & 7);
    const int sA = (lane >> 4) * 16;
    const int rB = ((lane >> 4) & 1) * 8 + (lane & 7);
    const int sB = ((lane >> 3) & 1) * 16;

    const int niter = K / 64;
    stage_load(0, 0);
    stage_load(64, 1);

    for (int i = 0; i < niter; i++) {
        cp_wait<1>();
        __syncthreads();   // data(i) visible; all warps done with stage (i-1)%3
        if (i + 2 < niter) stage_load((i + 2) * 64, (i + 2) % 3);
        else cp_commit();                  // keep group count aligned

        uint32_t slot = sbase + (i % 3) * STAGE_BYTES;
#pragma unroll
        for (int kk = 0; kk < 4; kk++) {
            uint32_t a[4][4], b[4][2];
#pragma unroll
            for (int im = 0; im < 4; im++) {
                int row = wm + im * 16 + rA;
                ldsm4(a[im][0], a[im][1], a[im][2], a[im][3],
                      slot + swz(row * 128 + kk * 32 + sA));
            }
#pragma unroll
            for (int p = 0; p < 2; p++) {
                int row = wn + p * 16 + rB;
                ldsm4(b[2 * p][0], b[2 * p][1], b[2 * p + 1][0], b[2 * p + 1][1],
                      slot + B_OFF + swz(row * 128 + kk * 32 + sB));
            }
#pragma unroll
            for (int im = 0; im < 4; im++)
#pragma unroll
                for (int jn = 0; jn < 4; jn++)
                    mma_f16(acc[im][jn], a[im], b[jn]);
        }
    }
    __syncthreads();       // protect smem before epilogue / exit
}

#define GEMM_SMEM_SETUP()                                                      \
    extern __shared__ char smem_raw[];                                         \
    char* sb = (char*)(((uintptr_t)smem_raw + 1023) & ~(uintptr_t)1023);       \
    uint32_t sbase = smem_u32(sb);                                             \
    const int lane = threadIdx.x & 31;                                         \
    const int wid = threadIdx.x >> 5;

// ---------------------------------------------------------------------------
// Kernel 0: all fp32 -> fp16 converts in ONE launch (y: 0=x, 1..3=weights)
// ---------------------------------------------------------------------------
__global__ __launch_bounds__(256) void cvt_all_kernel(
    const float* __restrict__ x, const float* __restrict__ wq,
    const float* __restrict__ wk, const float* __restrict__ wv) {
    const int which = blockIdx.y;
    const float* src;
    __half* dst;
    int n4;
    if (which == 0) {
        src = x;
        dst = g_hx;
        n4 = Bn * Ln * Hn / 4;
    } else {
        src = (which == 1) ? wq : (which == 2) ? wk : wv;
        dst = (which == 1) ? g_hwq : (which == 2) ? g_hwk : g_hwv;
        n4 = Hn * Hn / 4;
    }
    for (int i = blockIdx.x * blockDim.x + threadIdx.x; i < n4;
         i += gridDim.x * blockDim.x) {
        float4 v = ((const float4*)src)[i];
        __half2 h0 = __floats2half2_rn(v.x, v.y);
        __half2 h1 = __floats2half2_rn(v.z, v.w);
        uint2 u;
        u.x = *(uint32_t*)&h0;
        u.y = *(uint32_t*)&h1;
        ((uint2*)dst)[i] = u;
    }
}

// ---------------------------------------------------------------------------
// Kernel 1: QKV projections (fp16 in/out). z selects q/k/v.
// q pre-scaled by 1/H. v written TRANSPOSED [b][h][l].
// ---------------------------------------------------------------------------
__global__ __launch_bounds__(NT, 2) void qkv_kernel(
    const float* __restrict__ bq, const float* __restrict__ bk,
    const float* __restrict__ bv) {
    const int z = blockIdx.z;
    const __half* W = (z == 0) ? g_hwq : (z == 1) ? g_hwk : g_hwv;
    const float* bias = (z == 0) ? bq : (z == 1) ? bk : bv;
    const float scale = (z == 0) ? (1.0f / (float)Hn) : 1.0f;

    GEMM_SMEM_SETUP();

    const __half* A = g_hx + (size_t)blockIdx.y * 128 * Hn;
    const __half* Bm = W + (size_t)blockIdx.x * 128 * Hn;
    float acc[4][4][4] = {};
    gemm_nt(A, Bm, Hn, Hn, Hn, sbase, acc);

    const int row0 = blockIdx.y * 128 + (wid >> 2) * 64 + (lane >> 2);
    const int col0 = blockIdx.x * 128 + (wid & 3) * 32 + (lane & 3) * 2;

    if (z < 2) {
        __half* out = (z == 0) ? g_q : g_k;
#pragma unroll
        for (int im = 0; im < 4; im++) {
#pragma unroll
            for (int jn = 0; jn < 4; jn++) {
                int r = row0 + im * 16;
                int c = col0 + jn * 8;
                float2 b2 = *(const float2*)&bias[c];
                __half2 h0 = __floats2half2_rn((acc[im][jn][0] + b2.x) * scale,
                                               (acc[im][jn][1] + b2.y) * scale);
                __half2 h1 = __floats2half2_rn((acc[im][jn][2] + b2.x) * scale,
                                               (acc[im][jn][3] + b2.y) * scale);
                *(__half2*)&out[(size_t)r * Hn + c] = h0;
                *(__half2*)&out[(size_t)(r + 8) * Hn + c] = h1;
            }
        }
    } else {
#pragma unroll
        for (int im = 0; im < 4; im++) {
            int r = row0 + im * 16;
            int b = r >> 11;               // r / Ln
            int l = r & (Ln - 1);
            size_t vb = (size_t)b * Hn * Ln;
#pragma unroll
            for (int jn = 0; jn < 4; jn++) {
                int c = col0 + jn * 8;
                float2 b2 = *(const float2*)&bias[c];
                g_vT[vb + (size_t)c * Ln + l]           = __float2half_rn(acc[im][jn][0] + b2.x);
                g_vT[vb + (size_t)(c + 1) * Ln + l]     = __float2half_rn(acc[im][jn][1] + b2.y);
                g_vT[vb + (size_t)c * Ln + l + 8]       = __float2half_rn(acc[im][jn][2] + b2.x);
                g_vT[vb + (size_t)(c + 1) * Ln + l + 8] = __float2half_rn(acc[im][jn][3] + b2.y);
            }
        }
    }
}

// ---------------------------------------------------------------------------
// Kernel 2: E = exp(q @ k^T), diagonal -> 0, fp16 out + DETERMINISTIC
// per-(row, 32-col-slab) partial sums into g_zp (distinct address per writer;
// no atomics). |s| < 0.1 so exp needs no max subtraction.
// ---------------------------------------------------------------------------
__global__ __launch_bounds__(NT, 2) void score_kernel() {
    const int bz = blockIdx.z;

    GEMM_SMEM_SETUP();

    const __half* A = g_q + (size_t)bz * Ln * Hn + (size_t)blockIdx.y * 128 * Hn;
    const __half* Bm = g_k + (size_t)bz * Ln * Hn + (size_t)blockIdx.x * 128 * Hn;
    float acc[4][4][4] = {};
    gemm_nt(A, Bm, Hn, Hn, Hn, sbase, acc);

    __half* out = g_e + (size_t)bz * Ln * Ln;
    const int row0 = blockIdx.y * 128 + (wid >> 2) * 64 + (lane >> 2);
    const int col0 = blockIdx.x * 128 + (wid & 3) * 32 + (lane & 3) * 2;
    const int slab = blockIdx.x * 4 + (wid & 3);   // 64 slabs of 32 cols

#pragma unroll
    for (int im = 0; im < 4; im++) {
        int r = row0 + im * 16;
        float sr = 0.0f, sr8 = 0.0f;
#pragma unroll
        for (int jn = 0; jn < 4; jn++) {
            int c = col0 + jn * 8;
            float v0 = (r == c)         ? 0.0f : __expf(acc[im][jn][0]);
            float v1 = (r == c + 1)     ? 0.0f : __expf(acc[im][jn][1]);
            float v2 = (r + 8 == c)     ? 0.0f : __expf(acc[im][jn][2]);
            float v3 = (r + 8 == c + 1) ? 0.0f : __expf(acc[im][jn][3]);
            sr += v0 + v1;
            sr8 += v2 + v3;
            *(__half2*)&out[(size_t)r * Ln + c] = __floats2half2_rn(v0, v1);
            *(__half2*)&out[(size_t)(r + 8) * Ln + c] = __floats2half2_rn(v2, v3);
        }
        // Reduce over the 4 column-lanes (lane bits [0:1]) of this row
        sr  += __shfl_xor_sync(0xffffffff, sr, 1);
        sr  += __shfl_xor_sync(0xffffffff, sr, 2);
        sr8 += __shfl_xor_sync(0xffffffff, sr8, 1);
        sr8 += __shfl_xor_sync(0xffffffff, sr8, 2);
        if ((lane & 3) == 0) {
            g_zp[((size_t)bz * Ln + r) * 64 + slab] = sr;
            g_zp[((size_t)bz * Ln + r + 8) * 64 + slab] = sr8;
        }
    }
}

// ---------------------------------------------------------------------------
// Kernel 3: invz — reduce 64 partials per row -> g_z = 1/sum.
// One warp per row; fully coalesced.
// ---------------------------------------------------------------------------
__global__ __launch_bounds__(256) void invz_kernel() {
    const int row = blockIdx.x * 8 + (threadIdx.x >> 5);
    const int lane = threadIdx.x & 31;
    const float* p = g_zp + (size_t)row * 64;
    float s = p[lane] + p[lane + 32];
#pragma unroll
    for (int m = 16; m > 0; m >>= 1) s += __shfl_xor_sync(0xffffffff, s, m);
    if (lane == 0) g_z[row] = 1.0f / s;
}

// ---------------------------------------------------------------------------
// Kernel 4: O = diag(invZ) * (E @ vT) per batch (NT GEMM), fp32 out.
// Champion 128x128 tiles.
// ---------------------------------------------------------------------------
__global__ __launch_bounds__(NT, 2) void pv_kernel(float* __restrict__ out) {
    const int bz = blockIdx.z;

    GEMM_SMEM_SETUP();

    const __half* A = g_e + (size_t)bz * Ln * Ln + (size_t)blockIdx.y * 128 * Ln;
    const __half* Bm = g_vT + (size_t)bz * Hn * Ln + (size_t)blockIdx.x * 128 * Ln;
    float acc[4][4][4] = {};
    gemm_nt(A, Bm, Ln, Ln, Ln, sbase, acc);

    float* o = out + (size_t)bz * Ln * Hn;
    const int row0 = blockIdx.y * 128 + (wid >> 2) * 64 + (lane >> 2);
    const int col0 = blockIdx.x * 128 + (wid & 3) * 32 + (lane & 3) * 2;

#pragma unroll
    for (int im = 0; im < 4; im++) {
        int r = row0 + im * 16;
        float z0 = g_z[(size_t)bz * Ln + r];
        float z1 = g_z[(size_t)bz * Ln + r + 8];
#pragma unroll
        for (int jn = 0; jn < 4; jn++) {
            int c = col0 + jn * 8;
            *(float2*)&o[(size_t)r * Hn + c] =
                make_float2(acc[im][jn][0] * z0, acc[im][jn][1] * z0);
            *(float2*)&o[(size_t)(r + 8) * Hn + c] =
                make_float2(acc[im][jn][2] * z1, acc[im][jn][3] * z1);
        }
    }
}

// ---------------------------------------------------------------------------
extern "C" void kernel_launch(void* const* d_in, const int* in_sizes, int n_in,
                              void* d_out, int out_size) {
    const float* x  = (const float*)d_in[0];
    const float* Wq = (const float*)d_in[1];
    const float* bq = (const float*)d_in[2];
    const float* Wk = (const float*)d_in[3];
    const float* bk = (const float*)d_in[4];
    const float* Wv = (const float*)d_in[5];
    const float* bv = (const float*)d_in[6];
    float* out = (float*)d_out;

    cudaFuncSetAttribute(qkv_kernel, cudaFuncAttributeMaxDynamicSharedMemorySize, (int)SMEM_BYTES);
    cudaFuncSetAttribute(score_kernel, cudaFuncAttributeMaxDynamicSharedMemorySize, (int)SMEM_BYTES);
    cudaFuncSetAttribute(pv_kernel, cudaFuncAttributeMaxDynamicSharedMemorySize, (int)SMEM_BYTES);

    // All converts in one launch: y=0 covers x with grid-stride; y=1..3 weights.
    cvt_all_kernel<<<dim3(4096, 4), 256>>>(x, Wq, Wk, Wv);

    dim3 blk(NT);
    // QKV: M = 16384 (128 tiles), N = 1024 (8 tiles), z in {q,k,v}
    qkv_kernel<<<dim3(8, 128, 3), blk, SMEM_BYTES>>>(bq, bk, bv);
    // Scores+exp+partial rowsums: per batch 2048x2048 -> (16, 16, 8)
    score_kernel<<<dim3(16, 16, Bn), blk, SMEM_BYTES>>>();
    // Reduce partials -> 1/Z (one warp per row)
    invz_kernel<<<Bn * Ln / 8, 256>>>();
    // Output (normalized in epilogue): per batch 2048x1024 -> (8, 16, 8)
    pv_kernel<<<dim3(8, 16, Bn), blk, SMEM_BYTES>>>(out);
}